// round 17
// baseline (speedup 1.0000x reference)
#include <cuda_runtime.h>
#include <cuda_bf16.h>
#include <math.h>

// Problem constants
#define NB   512
#define NA   4
#define NE   10
#define NH   256
#define NOBS 2
#define NPHY 3
#define NG   3
#define NMV  2
#define NT   10
#define MP   (NB*NA*NE)   // 20480 rows for physical module
#define MA_  (NB*NA)      // 2048 rows for action module
#define KA   544          // padded action inner dim
#define K2FG 144          // (KA-256)/2 : packed feat(128)+goals/pad(16)

// ---------------- scratch (device globals; no runtime allocation) ----------------
__device__ __align__(16) float g_giP [MP*768];
__device__ __align__(16) float g_mp  [2*MP*NH];     // fp32 physical memory ping-pong
__device__ __align__(16) float g_ma  [2*MA_*NH];    // fp32 action memory ping-pong
__device__ __align__(16) float g_proc[MP*NH];

// packed bf16 hi/lo activation planes: [buf][plane][m][K/2] flattened
__device__ __align__(16) unsigned g_pkMp   [2*2*MP*128];
__device__ __align__(16) unsigned g_pkMan  [2*2*MA_*128];
__device__ __align__(16) unsigned g_catFG  [2*MA_*K2FG];  // feat+goals part of cat (k 256..543)

// packed bf16 hi/lo weight planes: [plane][n][K/2]
__device__ __align__(16) unsigned g_pkWhh [2*768*128];
__device__ __align__(16) unsigned g_pkWfcP[2*256*128];
__device__ __align__(16) unsigned g_pkWfcA[2*256*128];
__device__ __align__(16) unsigned g_pkWm1 [2*256*128];
__device__ __align__(16) unsigned g_pkWcat[2*1024*272];

__device__ __forceinline__ float sigf(float x){ return 1.f/(1.f+expf(-x)); }
__device__ __forceinline__ float eluf(float x){ return x>0.f ? x : expm1f(x); }

__device__ __forceinline__ void split2(float a, float b, unsigned& hi, unsigned& lo){
  __nv_bfloat16 ah = __float2bfloat16_rn(a);
  __nv_bfloat16 bh = __float2bfloat16_rn(b);
  float ar = a - __bfloat162float(ah);
  float br = b - __bfloat162float(bh);
  __nv_bfloat16 al = __float2bfloat16_rn(ar);
  __nv_bfloat16 bl = __float2bfloat16_rn(br);
  hi = ((unsigned)__bfloat16_as_ushort(bh) << 16) | (unsigned)__bfloat16_as_ushort(ah);
  lo = ((unsigned)__bfloat16_as_ushort(bl) << 16) | (unsigned)__bfloat16_as_ushort(al);
}

__device__ __forceinline__ void mma_bf16(float* c, unsigned a0, unsigned a1, unsigned a2, unsigned a3,
                                         unsigned b0, unsigned b1){
  asm volatile(
    "mma.sync.aligned.m16n8k16.row.col.f32.bf16.bf16.f32 "
    "{%0,%1,%2,%3}, {%4,%5,%6,%7}, {%8,%9}, {%0,%1,%2,%3};\n"
    : "+f"(c[0]), "+f"(c[1]), "+f"(c[2]), "+f"(c[3])
    : "r"(a0), "r"(a1), "r"(a2), "r"(a3), "r"(b0), "r"(b1));
}

// ldmatrix x4 (non-transposed). Lane addressing supplied by caller offset formula.
__device__ __forceinline__ void ldsm4(unsigned* r, const unsigned* p){
  unsigned a = (unsigned)__cvta_generic_to_shared(p);
  asm volatile("ldmatrix.sync.aligned.m8n8.x4.shared.b16 {%0,%1,%2,%3}, [%4];\n"
    : "=r"(r[0]), "=r"(r[1]), "=r"(r[2]), "=r"(r[3]) : "r"(a));
}

// A-operand lane offset (rows = m, 16 rows, pitch P uint32): tiles [m0-7 klo][m8-15 klo][m0-7 khi][m8-15 khi]
__device__ __forceinline__ int ldsmA_off(int lane, int P){
  return (lane & 15)*P + (lane >> 4)*4;
}
// B-operand lane offset (rows = n, 16 rows = 2 frags): tiles [n0-7 klo][n0-7 khi][n8-15 klo][n8-15 khi]
// -> r0,r1 = frag(n0-7) b0,b1 ; r2,r3 = frag(n8-15) b0,b1
__device__ __forceinline__ int ldsmB_off(int lane, int P){
  return ((lane >> 4)*8 + (lane & 7))*P + ((lane >> 3) & 1)*4;
}

// ---------------- cp.async helpers ----------------
__device__ __forceinline__ void cp16(unsigned* s, const unsigned* g){
  unsigned sa = (unsigned)__cvta_generic_to_shared(s);
  asm volatile("cp.async.cg.shared.global [%0], [%1], 16;\n" :: "r"(sa), "l"(g));
}
__device__ __forceinline__ void cp_commit(){ asm volatile("cp.async.commit_group;\n" ::: "memory"); }
template<int N> __device__ __forceinline__ void cp_wait(){
  asm volatile("cp.async.wait_group %0;\n" :: "n"(N) : "memory");
}

// ---------------- smem staging (packed source; BK=16; row = 8 payload + 4 pad uint32) ----------------
template<int BM>
__device__ __forceinline__ void stageApk(const unsigned* __restrict__ hi, const unsigned* __restrict__ lo,
                                         int K2, int m0, int k0, unsigned* sAhi, unsigned* sAlo){
  #pragma unroll
  for (int i = 0; i < BM/64; i++){
    int idx = threadIdx.x + i*256;
    int row = idx >> 2, p = (idx >> 1) & 1, c = idx & 1;
    const unsigned* src = (p ? lo : hi) + (size_t)(m0+row)*K2 + (k0>>1) + c*4;
    unsigned* dst = (p ? sAlo : sAhi) + row*12 + c*4;
    cp16(dst, src);
  }
}

template<int ROWS, int SW>
__device__ __forceinline__ void stageBpk(const unsigned* __restrict__ pk, int K2, int planeStride,
                                         int n0, int k0, unsigned* sBhi, unsigned* sBlo){
  #pragma unroll
  for (int i = 0; i < (ROWS*4 + 255)/256; i++){
    int idx = threadIdx.x + i*256;
    if ((ROWS*4) % 256 != 0 && idx >= ROWS*4) break;
    int r = idx >> 2, p = (idx >> 1) & 1, c = idx & 1;
    int srcn = (r/SW)*256 + n0 + (r%SW);
    const unsigned* src = pk + (size_t)p*planeStride + (size_t)srcn*K2 + (k0>>1) + c*4;
    unsigned* dst = (p ? sBlo : sBhi) + r*12 + c*4;
    cp16(dst, src);
  }
}

__device__ __forceinline__ void stageA_act(const unsigned* __restrict__ maHi, const unsigned* __restrict__ maLo,
                                           const unsigned* __restrict__ fgHi, const unsigned* __restrict__ fgLo,
                                           int m0, int k0, unsigned* sAhi, unsigned* sAlo){
  #pragma unroll
  for (int i = 0; i < 2; i++){
    int idx = threadIdx.x + i*256;
    int row = idx >> 2, p = (idx >> 1) & 1, c = idx & 1;
    const unsigned* src;
    if (k0 < 256) src = (p ? maLo : maHi) + (size_t)(m0+row)*128  + (k0>>1)       + c*4;
    else          src = (p ? fgLo : fgHi) + (size_t)(m0+row)*K2FG + ((k0-256)>>1) + c*4;
    unsigned* dst = (p ? sAlo : sAhi) + row*12 + c*4;
    cp16(dst, src);
  }
}

// ---------------- precompute kernels ----------------
__global__ void k_packW(const float* __restrict__ W, unsigned* __restrict__ pk, int N, int K){
  int idx = blockIdx.x*blockDim.x + threadIdx.x;
  int K2 = K >> 1;
  int half = N*K2;
  if (idx >= half) return;
  int n = idx / K2, kq = idx % K2;
  unsigned hi, lo;
  split2(W[(size_t)n*K + 2*kq], W[(size_t)n*K + 2*kq + 1], hi, lo);
  pk[idx] = hi; pk[half + idx] = lo;
}

__device__ __forceinline__ float wcat_val(const float* Wih, const float* Whh, int n, int k){
  int strip = n >> 8, j = n & 255;
  if (strip < 2){
    int o = strip*256 + j;
    if (k < 256)      return Whh[o*256 + k];
    else if (k < 515) return Wih[o*259 + (k-256)];
    return 0.f;
  } else if (strip == 2){
    if (k >= 256 && k < 515) return Wih[(512+j)*259 + (k-256)];
    return 0.f;
  } else {
    if (k < 256) return Whh[(512+j)*256 + k];
    return 0.f;
  }
}
__global__ void k_packWcat(const float* __restrict__ Wih, const float* __restrict__ Whh,
                           unsigned* __restrict__ pk){
  int idx = blockIdx.x*blockDim.x + threadIdx.x;
  if (idx >= 1024*272) return;
  int n = idx / 272, kq = idx % 272;
  unsigned hi, lo;
  split2(wcat_val(Wih, Whh, n, 2*kq), wcat_val(Wih, Whh, n, 2*kq+1), hi, lo);
  pk[idx] = hi; pk[1024*272 + idx] = lo;
}

__global__ void k_packAct(const float* __restrict__ X, unsigned* __restrict__ hi,
                          unsigned* __restrict__ lo, int npairs){
  int idx = blockIdx.x*blockDim.x + threadIdx.x;
  if (idx >= npairs) return;
  unsigned h, l;
  split2(X[2*idx], X[2*idx+1], h, l);
  hi[idx] = h; lo[idx] = l;
}

__global__ void k_packGoals(const float* __restrict__ goals){
  int idx = blockIdx.x*blockDim.x + threadIdx.x;
  if (idx >= MA_*16) return;
  int m = idx >> 4, q = idx & 15;
  float a = (2*q   < 3) ? goals[m*3 + 2*q]   : 0.f;
  float b = (2*q+1 < 3) ? goals[m*3 + 2*q+1] : 0.f;
  unsigned h, l;
  split2(a, b, h, l);
  g_catFG[(size_t)m*K2FG + 128 + q] = h;
  g_catFG[(size_t)MA_*K2FG + (size_t)m*K2FG + 128 + q] = l;
}

__global__ void k_giP(const float* __restrict__ obs, const float* __restrict__ phys,
                      const float* __restrict__ Wih, const float* __restrict__ bih,
                      const float* __restrict__ bhh){
  int m = blockIdx.x, j = threadIdx.x;
  int b = m / (NA*NE);
  int e = m % NE;
  float x0 = obs[m*NOBS+0], x1 = obs[m*NOBS+1];
  const float* p = phys + (b*NE + e)*NPHY;
  float x2 = p[0], x3 = p[1], x4 = p[2];
  #pragma unroll
  for (int g=0; g<3; g++){
    int o = g*256 + j;
    const float* w = Wih + o*5;
    float v = x0*w[0] + x1*w[1] + x2*w[2] + x3*w[3] + x4*w[4] + bih[o];
    if (g < 2) v += bhh[o];
    g_giP[(size_t)m*768 + o] = v;
  }
}

// ---------------- per-step mma kernels (pipelined, 1 barrier/tile, ldmatrix) ----------------
// Physical GRU: BM=128, 32 h-cols/block, 3 strips (r,z,hn). 8 warps, warp-tile 16x96.
__global__ void __launch_bounds__(256) k_step_phys(
    const float* __restrict__ mp, float* __restrict__ hout,
    const unsigned* __restrict__ aHi, const unsigned* __restrict__ aLo,
    unsigned* __restrict__ oHi, unsigned* __restrict__ oLo,
    const float* __restrict__ bhh)
{
  __shared__ __align__(16) unsigned sAhi[2][128*12], sAlo[2][128*12];
  __shared__ __align__(16) unsigned sBhi[2][96*12],  sBlo[2][96*12];
  const int m0 = blockIdx.x*128, n0 = blockIdx.y*32;
  const int lane = threadIdx.x & 31, w = threadIdx.x >> 5;
  float acc[3][4][4];
  #pragma unroll
  for (int s=0;s<3;s++)
    #pragma unroll
    for (int f=0;f<4;f++)
      #pragma unroll
      for (int c=0;c<4;c++) acc[s][f][c]=0.f;

  constexpr int KT = 16;
  stageApk<128>(aHi, aLo, 128, m0, 0, sAhi[0], sAlo[0]);
  stageBpk<96,32>(g_pkWhh, 128, 768*128, n0, 0, sBhi[0], sBlo[0]);
  cp_commit();
  const int aoff = (w*16)*12 + ldsmA_off(lane, 12);
  const int boff = ldsmB_off(lane, 12);
  for (int kt=0; kt<KT; ++kt){
    cp_wait<0>();
    __syncthreads();
    if (kt+1 < KT){
      stageApk<128>(aHi, aLo, 128, m0, (kt+1)*16, sAhi[(kt+1)&1], sAlo[(kt+1)&1]);
      stageBpk<96,32>(g_pkWhh, 128, 768*128, n0, (kt+1)*16, sBhi[(kt+1)&1], sBlo[(kt+1)&1]);
      cp_commit();
    }
    const int b = kt & 1;
    unsigned ah[4], al[4];
    ldsm4(ah, sAhi[b] + aoff);
    ldsm4(al, sAlo[b] + aoff);
    #pragma unroll
    for (int s=0;s<3;s++){
      #pragma unroll
      for (int fp=0; fp<2; fp++){
        unsigned bh[4], bl[4];
        int bb = (s*32 + fp*16)*12 + boff;
        ldsm4(bh, sBhi[b] + bb);
        ldsm4(bl, sBlo[b] + bb);
        mma_bf16(acc[s][2*fp],   ah[0],ah[1],ah[2],ah[3], bh[0],bh[1]);
        mma_bf16(acc[s][2*fp],   ah[0],ah[1],ah[2],ah[3], bl[0],bl[1]);
        mma_bf16(acc[s][2*fp],   al[0],al[1],al[2],al[3], bh[0],bh[1]);
        mma_bf16(acc[s][2*fp+1], ah[0],ah[1],ah[2],ah[3], bh[2],bh[3]);
        mma_bf16(acc[s][2*fp+1], ah[0],ah[1],ah[2],ah[3], bl[2],bl[3]);
        mma_bf16(acc[s][2*fp+1], al[0],al[1],al[2],al[3], bh[2],bh[3]);
      }
    }
  }
  // fused GRU epilogue + packed output planes
  int mb = m0 + w*16 + (lane>>2);
  int jb0 = 2*(lane&3);
  #pragma unroll
  for (int mr=0; mr<2; mr++){
    int m = mb + mr*8;
    const float* gi = g_giP + (size_t)m*768;
    #pragma unroll
    for (int f=0; f<4; f++){
      float o[2];
      #pragma unroll
      for (int c=0; c<2; c++){
        int j = n0 + jb0 + f*8 + c;
        int ci = mr*2 + c;
        float r = sigf(acc[0][f][ci] + gi[j]);
        float z = sigf(acc[1][f][ci] + gi[256+j]);
        float n = tanhf(gi[512+j] + r*(acc[2][f][ci] + bhh[512+j]));
        o[c] = (1.f - z)*n + z*mp[(size_t)m*256 + j];
      }
      int j0 = n0 + jb0 + f*8;
      *(float2*)(hout + (size_t)m*256 + j0) = make_float2(o[0], o[1]);
      unsigned hi, lo;
      split2(o[0], o[1], hi, lo);
      oHi[(size_t)m*128 + (j0>>1)] = hi;
      oLo[(size_t)m*128 + (j0>>1)] = lo;
    }
  }
}

// FC + ELU (fp32 out): BM=64, BN=64, warps 2x4, warp-tile 32x16. K=256.
__global__ void __launch_bounds__(256) k_fc_elu(
    const unsigned* __restrict__ aHi, const unsigned* __restrict__ aLo,
    const unsigned* __restrict__ pkW, const float* __restrict__ bias,
    float* __restrict__ Y)
{
  __shared__ __align__(16) unsigned sAhi[2][64*12], sAlo[2][64*12];
  __shared__ __align__(16) unsigned sBhi[2][64*12], sBlo[2][64*12];
  const int m0 = blockIdx.x*64, n0 = blockIdx.y*64;
  const int lane = threadIdx.x & 31, w = threadIdx.x >> 5;
  const int wm = (w>>2)*32, wn = (w&3)*16;
  float acc[2][2][4];
  #pragma unroll
  for (int a=0;a<2;a++)
    #pragma unroll
    for (int b=0;b<2;b++)
      #pragma unroll
      for (int c=0;c<4;c++) acc[a][b][c]=0.f;

  constexpr int KT = 16;
  stageApk<64>(aHi, aLo, 128, m0, 0, sAhi[0], sAlo[0]);
  stageBpk<64,64>(pkW, 128, 256*128, n0, 0, sBhi[0], sBlo[0]);
  cp_commit();
  const int aoffL = ldsmA_off(lane, 12);
  const int boff = wn*12 + ldsmB_off(lane, 12);
  for (int kt=0; kt<KT; ++kt){
    cp_wait<0>();
    __syncthreads();
    if (kt+1 < KT){
      stageApk<64>(aHi, aLo, 128, m0, (kt+1)*16, sAhi[(kt+1)&1], sAlo[(kt+1)&1]);
      stageBpk<64,64>(pkW, 128, 256*128, n0, (kt+1)*16, sBhi[(kt+1)&1], sBlo[(kt+1)&1]);
      cp_commit();
    }
    const int b = kt & 1;
    unsigned ah[2][4], al[2][4], bh[4], bl[4];
    #pragma unroll
    for (int mf=0; mf<2; mf++){
      int ao = (wm + mf*16)*12 + aoffL;
      ldsm4(ah[mf], sAhi[b] + ao);
      ldsm4(al[mf], sAlo[b] + ao);
    }
    ldsm4(bh, sBhi[b] + boff);
    ldsm4(bl, sBlo[b] + boff);
    #pragma unroll
    for (int mf=0; mf<2; mf++){
      mma_bf16(acc[mf][0], ah[mf][0],ah[mf][1],ah[mf][2],ah[mf][3], bh[0],bh[1]);
      mma_bf16(acc[mf][0], ah[mf][0],ah[mf][1],ah[mf][2],ah[mf][3], bl[0],bl[1]);
      mma_bf16(acc[mf][0], al[mf][0],al[mf][1],al[mf][2],al[mf][3], bh[0],bh[1]);
      mma_bf16(acc[mf][1], ah[mf][0],ah[mf][1],ah[mf][2],ah[mf][3], bh[2],bh[3]);
      mma_bf16(acc[mf][1], ah[mf][0],ah[mf][1],ah[mf][2],ah[mf][3], bl[2],bl[3]);
      mma_bf16(acc[mf][1], al[mf][0],al[mf][1],al[mf][2],al[mf][3], bh[2],bh[3]);
    }
  }
  int mb = m0 + wm + (lane>>2);
  int nb0 = n0 + wn + 2*(lane&3);
  #pragma unroll
  for (int mf=0; mf<2; mf++)
    #pragma unroll
    for (int mr=0; mr<2; mr++){
      int m = mb + mf*16 + mr*8;
      #pragma unroll
      for (int nf=0; nf<2; nf++){
        float o0 = eluf(acc[mf][nf][mr*2+0] + bias[nb0 + nf*8]);
        float o1 = eluf(acc[mf][nf][mr*2+1] + bias[nb0 + nf*8 + 1]);
        *(float2*)(Y + (size_t)m*256 + nb0 + nf*8) = make_float2(o0, o1);
      }
    }
}

// Action GRU: BM=128, 16 h-cols/block, 4 strips (r,z,in,hn). K=544.
__global__ void __launch_bounds__(256) k_step_act(
    const float* __restrict__ ma, float* __restrict__ haout,
    const unsigned* __restrict__ maHi, const unsigned* __restrict__ maLo,
    const unsigned* __restrict__ fgHi, const unsigned* __restrict__ fgLo,
    unsigned* __restrict__ oHi, unsigned* __restrict__ oLo,
    const float* __restrict__ bih, const float* __restrict__ bhh)
{
  __shared__ __align__(16) unsigned sAhi[2][128*12], sAlo[2][128*12];
  __shared__ __align__(16) unsigned sBhi[2][64*12],  sBlo[2][64*12];
  const int m0 = blockIdx.x*128, n0 = blockIdx.y*16;
  const int lane = threadIdx.x & 31, w = threadIdx.x >> 5;
  float acc[4][2][4];
  #pragma unroll
  for (int s=0;s<4;s++)
    #pragma unroll
    for (int f=0;f<2;f++)
      #pragma unroll
      for (int c=0;c<4;c++) acc[s][f][c]=0.f;

  constexpr int KT = KA/16;   // 34
  stageA_act(maHi, maLo, fgHi, fgLo, m0, 0, sAhi[0], sAlo[0]);
  stageBpk<64,16>(g_pkWcat, 272, 1024*272, n0, 0, sBhi[0], sBlo[0]);
  cp_commit();
  const int aoff = (w*16)*12 + ldsmA_off(lane, 12);
  const int boff = ldsmB_off(lane, 12);
  for (int kt=0; kt<KT; ++kt){
    cp_wait<0>();
    __syncthreads();
    if (kt+1 < KT){
      stageA_act(maHi, maLo, fgHi, fgLo, m0, (kt+1)*16, sAhi[(kt+1)&1], sAlo[(kt+1)&1]);
      stageBpk<64,16>(g_pkWcat, 272, 1024*272, n0, (kt+1)*16, sBhi[(kt+1)&1], sBlo[(kt+1)&1]);
      cp_commit();
    }
    const int b = kt & 1;
    unsigned ah[4], al[4];
    ldsm4(ah, sAhi[b] + aoff);
    ldsm4(al, sAlo[b] + aoff);
    #pragma unroll
    for (int s=0;s<4;s++){
      unsigned bh[4], bl[4];
      int bb = (s*16)*12 + boff;
      ldsm4(bh, sBhi[b] + bb);
      ldsm4(bl, sBlo[b] + bb);
      mma_bf16(acc[s][0], ah[0],ah[1],ah[2],ah[3], bh[0],bh[1]);
      mma_bf16(acc[s][0], ah[0],ah[1],ah[2],ah[3], bl[0],bl[1]);
      mma_bf16(acc[s][0], al[0],al[1],al[2],al[3], bh[0],bh[1]);
      mma_bf16(acc[s][1], ah[0],ah[1],ah[2],ah[3], bh[2],bh[3]);
      mma_bf16(acc[s][1], ah[0],ah[1],ah[2],ah[3], bl[2],bl[3]);
      mma_bf16(acc[s][1], al[0],al[1],al[2],al[3], bh[2],bh[3]);
    }
  }
  int mb = m0 + w*16 + (lane>>2);
  int jb0 = 2*(lane&3);
  #pragma unroll
  for (int mr=0; mr<2; mr++){
    int m = mb + mr*8;
    #pragma unroll
    for (int f=0; f<2; f++){
      float o[2];
      #pragma unroll
      for (int c=0; c<2; c++){
        int j = n0 + jb0 + f*8 + c;
        int ci = mr*2 + c;
        float r = sigf(acc[0][f][ci] + bih[j]     + bhh[j]);
        float z = sigf(acc[1][f][ci] + bih[256+j] + bhh[256+j]);
        float n = tanhf(acc[2][f][ci] + bih[512+j] + r*(acc[3][f][ci] + bhh[512+j]));
        o[c] = (1.f - z)*n + z*ma[(size_t)m*256 + j];
      }
      int j0 = n0 + jb0 + f*8;
      *(float2*)(haout + (size_t)m*256 + j0) = make_float2(o[0], o[1]);
      unsigned hi, lo;
      split2(o[0], o[1], hi, lo);
      oHi[(size_t)m*128 + (j0>>1)] = hi;
      oLo[(size_t)m*128 + (j0>>1)] = lo;
    }
  }
}

// ---------------- fused action tail: proca = elu(man@WfcA^T+b); m1 = elu(proca@Wm1^T+b);
// out = tanh(m1@W2^T+b2)*0.05.  BM=16 rows per block, 128 blocks, everything stays in smem.
#define PF 132   // full-K plane pitch (128 pairs + 4 pad)
#define PM 264   // m1 fp32 row pitch (floats); 16*264*4 = 16896B = sizeof(sA)
__global__ void __launch_bounds__(256) k_act_tail(
    const unsigned* __restrict__ aHi, const unsigned* __restrict__ aLo,
    const float* __restrict__ bfca, const float* __restrict__ bm1,
    const float* __restrict__ W2, const float* __restrict__ b2,
    float* __restrict__ out)
{
  __shared__ __align__(16) unsigned sA[2][16*PF];   // input planes; later aliased as sM (fp32 m1)
  __shared__ __align__(16) unsigned sB[2][128*12];
  __shared__ __align__(16) unsigned sC[2][16*PF];   // proca planes
  float* sM = (float*)&sA[0][0];
  const int m0 = blockIdx.x*16;
  const int tid = threadIdx.x, lane = tid & 31, w = tid >> 5;

  // load full-K A planes (16 rows x 128 pairs x 2 planes)
  #pragma unroll
  for (int i=0;i<4;i++){
    int idx = tid + i*256;          // 1024 chunks of 16B
    int p = idx >> 9;
    int rem = idx & 511;
    int r = rem >> 5, c4 = rem & 31;
    uint4 v = *(const uint4*)((p ? aLo : aHi) + (size_t)(m0+r)*128 + c4*4);
    *(uint4*)(sA[p] + r*PF + c4*4) = v;
  }
  __syncthreads();

  const int aoffL = ldsmA_off(lane, PF);
  const int boff  = w*16*12 + ldsmB_off(lane, 12);

  // ---- phase 1: proca ----
  {
    float acc[2][2][4];
    #pragma unroll
    for (int h=0;h<2;h++)
      #pragma unroll
      for (int f=0;f<2;f++)
        #pragma unroll
        for (int c=0;c<4;c++) acc[h][f][c]=0.f;
    #pragma unroll 1
    for (int h=0; h<2; h++){
      #pragma unroll 1
      for (int kt=0; kt<16; kt++){
        #pragma unroll
        for (int i=0;i<2;i++){
          int idx = tid + i*256;    // 512: 128 rows x 2 chunks x 2 planes
          int p = idx >> 8; int rem = idx & 255;
          int r = rem >> 1, c4 = rem & 1;
          uint4 v = *(const uint4*)(g_pkWfcA + (size_t)p*(256*128) + (size_t)(h*128+r)*128 + kt*8 + c4*4);
          *(uint4*)(sB[p] + r*12 + c4*4) = v;
        }
        __syncthreads();
        unsigned ah[4], al[4], bh[4], bl[4];
        ldsm4(ah, sA[0] + aoffL + kt*8);
        ldsm4(al, sA[1] + aoffL + kt*8);
        ldsm4(bh, sB[0] + boff);
        ldsm4(bl, sB[1] + boff);
        mma_bf16(acc[h][0], ah[0],ah[1],ah[2],ah[3], bh[0],bh[1]);
        mma_bf16(acc[h][0], ah[0],ah[1],ah[2],ah[3], bl[0],bl[1]);
        mma_bf16(acc[h][0], al[0],al[1],al[2],al[3], bh[0],bh[1]);
        mma_bf16(acc[h][1], ah[0],ah[1],ah[2],ah[3], bh[2],bh[3]);
        mma_bf16(acc[h][1], ah[0],ah[1],ah[2],ah[3], bl[2],bl[3]);
        mma_bf16(acc[h][1], al[0],al[1],al[2],al[3], bh[2],bh[3]);
        __syncthreads();
      }
    }
    // epilogue -> sC packed planes
    #pragma unroll
    for (int h=0;h<2;h++)
      #pragma unroll
      for (int f=0;f<2;f++){
        int n0 = h*128 + w*16 + f*8;
        int col = n0 + 2*(lane&3);
        #pragma unroll
        for (int mr=0; mr<2; mr++){
          int m = (lane>>2) + mr*8;
          float o0 = eluf(acc[h][f][mr*2+0] + bfca[col]);
          float o1 = eluf(acc[h][f][mr*2+1] + bfca[col+1]);
          unsigned hi, lo;
          split2(o0, o1, hi, lo);
          sC[0][m*PF + (n0>>1) + (lane&3)] = hi;
          sC[1][m*PF + (n0>>1) + (lane&3)] = lo;
        }
      }
  }
  __syncthreads();

  // ---- phase 2: m1 ----
  {
    float acc[2][2][4];
    #pragma unroll
    for (int h=0;h<2;h++)
      #pragma unroll
      for (int f=0;f<2;f++)
        #pragma unroll
        for (int c=0;c<4;c++) acc[h][f][c]=0.f;
    #pragma unroll 1
    for (int h=0; h<2; h++){
      #pragma unroll 1
      for (int kt=0; kt<16; kt++){
        #pragma unroll
        for (int i=0;i<2;i++){
          int idx = tid + i*256;
          int p = idx >> 8; int rem = idx & 255;
          int r = rem >> 1, c4 = rem & 1;
          uint4 v = *(const uint4*)(g_pkWm1 + (size_t)p*(256*128) + (size_t)(h*128+r)*128 + kt*8 + c4*4);
          *(uint4*)(sB[p] + r*12 + c4*4) = v;
        }
        __syncthreads();
        unsigned ah[4], al[4], bh[4], bl[4];
        ldsm4(ah, sC[0] + aoffL + kt*8);
        ldsm4(al, sC[1] + aoffL + kt*8);
        ldsm4(bh, sB[0] + boff);
        ldsm4(bl, sB[1] + boff);
        mma_bf16(acc[h][0], ah[0],ah[1],ah[2],ah[3], bh[0],bh[1]);
        mma_bf16(acc[h][0], ah[0],ah[1],ah[2],ah[3], bl[0],bl[1]);
        mma_bf16(acc[h][0], al[0],al[1],al[2],al[3], bh[0],bh[1]);
        mma_bf16(acc[h][1], ah[0],ah[1],ah[2],ah[3], bh[2],bh[3]);
        mma_bf16(acc[h][1], ah[0],ah[1],ah[2],ah[3], bl[2],bl[3]);
        mma_bf16(acc[h][1], al[0],al[1],al[2],al[3], bh[2],bh[3]);
        __syncthreads();
      }
    }
    // epilogue -> sM fp32 (aliases sA; phase2 no longer reads sA)
    __syncthreads();
    #pragma unroll
    for (int h=0;h<2;h++)
      #pragma unroll
      for (int f=0;f<2;f++){
        int n0 = h*128 + w*16 + f*8;
        int col = n0 + 2*(lane&3);
        #pragma unroll
        for (int mr=0; mr<2; mr++){
          int m = (lane>>2) + mr*8;
          sM[m*PM + col]     = eluf(acc[h][f][mr*2+0] + bm1[col]);
          sM[m*PM + col + 1] = eluf(acc[h][f][mr*2+1] + bm1[col+1]);
        }
      }
  }
  __syncthreads();

  // ---- phase 3: movement head ----
  #pragma unroll
  for (int rr=0; rr<2; rr++){
    int r = w*2 + rr;
    float s0 = 0.f, s1 = 0.f;
    #pragma unroll
    for (int k=lane; k<256; k+=32){
      float x = sM[r*PM + k];
      s0 = fmaf(x, W2[k],       s0);
      s1 = fmaf(x, W2[256 + k], s1);
    }
    #pragma unroll
    for (int o=16;o>0;o>>=1){
      s0 += __shfl_down_sync(0xffffffffu, s0, o);
      s1 += __shfl_down_sync(0xffffffffu, s1, o);
    }
    if (lane == 0){
      out[(size_t)(m0 + r)*2 + 0] = tanhf(s0 + b2[0]) * 0.05f;
      out[(size_t)(m0 + r)*2 + 1] = tanhf(s1 + b2[1]) * 0.05f;
    }
  }
}

// ---------------- small kernels ----------------
__global__ void k_maxpoolpack(const float* __restrict__ proc){
  int g = blockIdx.x;       // 0..2047
  int c = threadIdx.x;      // 0..127 (col pair)
  const float* p = proc + (size_t)g*NE*256;
  float v0 = p[2*c], v1 = p[2*c+1];
  #pragma unroll
  for (int e=1;e<NE;e++){
    v0 = fmaxf(v0, p[e*256 + 2*c]);
    v1 = fmaxf(v1, p[e*256 + 2*c + 1]);
  }
  unsigned hi, lo;
  split2(v0, v1, hi, lo);
  g_catFG[(size_t)g*K2FG + c] = hi;
  g_catFG[(size_t)MA_*K2FG + (size_t)g*K2FG + c] = lo;
}

// ---------------- launch ----------------
extern "C" void kernel_launch(void* const* d_in, const int* in_sizes, int n_in,
                              void* d_out, int out_size){
  (void)in_sizes; (void)n_in; (void)out_size;
  const float* obs  = (const float*)d_in[0];
  const float* phys = (const float*)d_in[1];
  const float* goals= (const float*)d_in[2];
  const float* memp = (const float*)d_in[3];
  const float* mema = (const float*)d_in[4];
  const float* Wihp = (const float*)d_in[5];
  const float* Whhp = (const float*)d_in[6];
  const float* bihp = (const float*)d_in[7];
  const float* bhhp = (const float*)d_in[8];
  const float* Wfcp = (const float*)d_in[9];
  const float* bfcp = (const float*)d_in[10];
  const float* Wiha = (const float*)d_in[11];
  const float* Whha = (const float*)d_in[12];
  const float* biha = (const float*)d_in[13];
  const float* bhha = (const float*)d_in[14];
  const float* Wfca = (const float*)d_in[15];
  const float* bfca = (const float*)d_in[16];
  const float* Wm1  = (const float*)d_in[17];
  const float* bm1  = (const float*)d_in[18];
  const float* Wm2  = (const float*)d_in[19];
  const float* bm2  = (const float*)d_in[20];
  float* out = (float*)d_out;

  float *Pmp, *Pma, *Pproc;
  unsigned *PpkMp, *PpkMan, *PcatFG;
  unsigned *PpkWhh, *PpkWfcP, *PpkWfcA, *PpkWm1, *PpkWcat;
  cudaGetSymbolAddress((void**)&Pmp,     g_mp);
  cudaGetSymbolAddress((void**)&Pma,     g_ma);
  cudaGetSymbolAddress((void**)&Pproc,   g_proc);
  cudaGetSymbolAddress((void**)&PpkMp,   g_pkMp);
  cudaGetSymbolAddress((void**)&PpkMan,  g_pkMan);
  cudaGetSymbolAddress((void**)&PcatFG,  g_catFG);
  cudaGetSymbolAddress((void**)&PpkWhh,  g_pkWhh);
  cudaGetSymbolAddress((void**)&PpkWfcP, g_pkWfcP);
  cudaGetSymbolAddress((void**)&PpkWfcA, g_pkWfcA);
  cudaGetSymbolAddress((void**)&PpkWm1,  g_pkWm1);
  cudaGetSymbolAddress((void**)&PpkWcat, g_pkWcat);

  const size_t SMP = (size_t)MP*128;
  const size_t SMA = (size_t)MA_*128;

  cudaMemcpyAsync(Pmp, memp, (size_t)MP *NH*sizeof(float), cudaMemcpyDeviceToDevice);
  cudaMemcpyAsync(Pma, mema, (size_t)MA_*NH*sizeof(float), cudaMemcpyDeviceToDevice);

  k_packW   <<<(768*128+255)/256, 256>>>(Whhp, PpkWhh, 768, 256);
  k_packW   <<<(256*128+255)/256, 256>>>(Wfcp, PpkWfcP, 256, 256);
  k_packW   <<<(256*128+255)/256, 256>>>(Wfca, PpkWfcA, 256, 256);
  k_packW   <<<(256*128+255)/256, 256>>>(Wm1,  PpkWm1,  256, 256);
  k_packWcat<<<(1024*272+255)/256,256>>>(Wiha, Whha, PpkWcat);
  k_packAct <<<(MP*128+255)/256,  256>>>(memp, PpkMp,  PpkMp  + SMP, MP*128);
  k_packAct <<<(MA_*128+255)/256, 256>>>(mema, PpkMan, PpkMan + SMA, MA_*128);
  k_packGoals<<<(MA_*16+255)/256, 256>>>(goals);
  k_giP<<<MP,256>>>(obs, phys, Wihp, bihp, bhhp);

  for (int t=0;t<NT;t++){
    int cur = t & 1, nxt = cur ^ 1;
    float* mpc = Pmp + (size_t)cur*MP *NH;
    float* mpn = Pmp + (size_t)nxt*MP *NH;
    float* mac = Pma + (size_t)cur*MA_*NH;
    float* man = Pma + (size_t)nxt*MA_*NH;
    unsigned* mpPkC = PpkMp  + (size_t)cur*2*SMP;
    unsigned* mpPkN = PpkMp  + (size_t)nxt*2*SMP;
    unsigned* maPkC = PpkMan + (size_t)cur*2*SMA;
    unsigned* maPkN = PpkMan + (size_t)nxt*2*SMA;

    k_step_phys<<<dim3(MP/128, 8), 256>>>(mpc, mpn, mpPkC, mpPkC + SMP,
                                          mpPkN, mpPkN + SMP, bhhp);
    k_fc_elu<<<dim3(MP/64, 4), 256>>>(mpPkN, mpPkN + SMP, PpkWfcP, bfcp, Pproc);
    k_maxpoolpack<<<MA_, 128>>>(Pproc);
    k_step_act<<<dim3(MA_/128, 16), 256>>>(mac, man, maPkC, maPkC + SMA,
                                           PcatFG, PcatFG + (size_t)MA_*K2FG,
                                           maPkN, maPkN + SMA, biha, bhha);
    k_act_tail<<<MA_/16, 256>>>(maPkN, maPkN + SMA, bfca, bm1, Wm2, bm2,
                                out + (size_t)t*MA_*NMV);
  }
}